// round 10
// baseline (speedup 1.0000x reference)
#include <cuda_runtime.h>
#include <cstdint>

#define HH 448
#define WW 512
#define HW (HH*WW)        // 229376
#define PHW 65536         // per-h activation [w][c] = 512*128

typedef unsigned long long ull;

// scratch (allocation-free rule)
__device__ float g_xr[(size_t)HH*WW*128];   // [h][w][c]
__device__ int   g_inds[HW];

__device__ __forceinline__ ull pk2(float v){
    ull r; unsigned u = __float_as_uint(v);
    asm("mov.b64 %0, {%1, %1};" : "=l"(r) : "r"(u));
    return r;
}
__device__ __forceinline__ void fma2(ull& d, ull a, ull b){
    asm("fma.rn.f32x2 %0, %1, %2, %0;" : "+l"(d) : "l"(a), "l"(b));
}
__device__ __forceinline__ float2 up2(ull v){
    unsigned lo, hi;
    asm("mov.b64 {%0, %1}, %2;" : "=r"(lo), "=r"(hi) : "l"(v));
    return make_float2(__uint_as_float(lo), __uint_as_float(hi));
}
__device__ __forceinline__ float lrelu(float v){ return v >= 0.f ? v : 0.01f*v; }

// ---- smem layout (floats) ----
// X    [128c][128w] @0       (16384)  -- single buffer, overwritten in place
// WsB  [2][16][128] @16384   (4096)   -- W double buffer; reused for argmax red.
// bias block       @20480    (641)
#define SM_X  0
#define SM_W  16384
#define SM_B  20480
#define SM_FLOATS (20480 + 648)

// One GEMM stage: acc[8o][4 f32x2-pairs] += W(128o x 128c) * X(128c x 128w).
// W streamed from global in 8 chunks of 16 k, double-buffered with XOR swizzle.
// X is smem-resident. If MASK: threads tid<128 also accumulate the 129th
// classifier row (mAcc partials, col = tid) from the resident X.
template<bool MASK>
__device__ __forceinline__ void run_stage(
    const float* __restrict__ Wg, const float* __restrict__ Xs,
    float* __restrict__ WsB, ull (&acc)[8][4],
    const float* __restrict__ wsm, float* __restrict__ mAcc)
{
    const int tid = threadIdx.x;
    const int og = tid >> 4, wg = tid & 15;
    const int o0 = og << 3, t4 = wg << 2;
    const int wq = tid & 3, wo = tid >> 2;

    float4 wst0, wst1;
    wst0 = *reinterpret_cast<const float4*>(Wg + wo*128 + wq*4);
    wst1 = *reinterpret_cast<const float4*>(Wg + (wo+64)*128 + wq*4);
    {
        const float* s0 = &wst0.x; const float* s1 = &wst1.x;
        #pragma unroll
        for (int i = 0; i < 4; ++i){
            int k = wq*4 + i;
            WsB[k*128 + (wo ^ (wq<<3))] = s0[i];
            WsB[k*128 + ((wo+64) ^ (wq<<3))] = s1[i];
        }
    }
    __syncthreads();

    int buf = 0;
    #pragma unroll 1
    for (int ch = 0; ch < 8; ++ch){
        if (ch < 7){
            int k0 = (ch+1)*16;
            wst0 = *reinterpret_cast<const float4*>(Wg + wo*128 + k0 + wq*4);
            wst1 = *reinterpret_cast<const float4*>(Wg + (wo+64)*128 + k0 + wq*4);
        }
        const float* Wb = WsB + buf*2048;
        const float* Xc = Xs + ch*16*128;
        #pragma unroll
        for (int k = 0; k < 16; ++k){
            int wOff = ((k >> 2) & 3) << 3;
            const float4* wr = reinterpret_cast<const float4*>(&Wb[k*128 + (o0 ^ wOff)]);
            float4 wa = wr[0], wb2 = wr[1];
            float wv[8] = {wa.x,wa.y,wa.z,wa.w,wb2.x,wb2.y,wb2.z,wb2.w};
            ulonglong2 v0 = *reinterpret_cast<const ulonglong2*>(&Xc[k*128 + t4]);
            ulonglong2 v1 = *reinterpret_cast<const ulonglong2*>(&Xc[k*128 + t4 + 64]);
            #pragma unroll
            for (int o = 0; o < 8; ++o){
                ull wp = pk2(wv[o]);
                fma2(acc[o][0], v0.x, wp);
                fma2(acc[o][1], v0.y, wp);
                fma2(acc[o][2], v1.x, wp);
                fma2(acc[o][3], v1.y, wp);
            }
        }
        if (MASK && tid < 128){
            #pragma unroll
            for (int k = 0; k < 16; k += 2){
                mAcc[0] = fmaf(Xc[k*128 + tid],     wsm[ch*16 + k],     mAcc[0]);
                mAcc[1] = fmaf(Xc[(k+1)*128 + tid], wsm[ch*16 + k + 1], mAcc[1]);
            }
        }
        if (ch < 7){
            int nb = buf ^ 1;
            float* d = WsB + nb*2048;
            const float* s0 = &wst0.x; const float* s1 = &wst1.x;
            #pragma unroll
            for (int i = 0; i < 4; ++i){
                int k = wq*4 + i;
                d[k*128 + (wo ^ (wq<<3))] = s0[i];
                d[k*128 + ((wo+64) ^ (wq<<3))] = s1[i];
            }
            __syncthreads();
            buf = nb;
        }
    }
}

#define ZERO_ACC() do { _Pragma("unroll") for(int o=0;o<8;o++){ _Pragma("unroll") for(int q=0;q<4;q++) acc[o][q]=0ull; } } while(0)

// Fused chain per (h, 128w) tile: reg1 -> xr; cl1 -> X (in place);
// cl2 -> X (in place); cl3 + mask + argmax -> inds/outMask.
// Single 64KB X buffer -> ~82KB smem -> 2 CTAs/SM (bubbles overlap).
__global__ void __launch_bounds__(256, 2)
k_fused(const float* __restrict__ x_in,
        const float* __restrict__ w_cl1, const float* __restrict__ b_cl1,
        const float* __restrict__ w_reg1, const float* __restrict__ b_reg1,
        const float* __restrict__ w_cl2, const float* __restrict__ b_cl2,
        const float* __restrict__ w_cl3, const float* __restrict__ b_cl3,
        float* __restrict__ xr, int* __restrict__ inds,
        float* __restrict__ outMask)
{
    extern __shared__ float sm[];
    float* X    = sm + SM_X;
    float* WsB  = sm + SM_W;
    float* biasA = sm + SM_B;          // cl1
    float* biasB = biasA + 128;        // reg1
    float* biasC = biasA + 256;        // cl2
    float* biasD = biasA + 384;        // cl3 (129)
    float* wsm   = biasA + 516;        // mask weight row (128)

    const int tid = threadIdx.x;
    const int h = blockIdx.y, wBase = blockIdx.x * 128;
    const int og = tid >> 4, wg = tid & 15;
    const int o0 = og << 3, t4 = wg << 2;

    // load X tile: x_in[c][h][w]
    {
        const float* xs = x_in + (size_t)h*WW + wBase;
        #pragma unroll 4
        for (int i = tid; i < 4096; i += 256){
            int c = i >> 5, f = i & 31;
            *reinterpret_cast<float4*>(&X[c*128 + f*4]) =
                *reinterpret_cast<const float4*>(xs + (size_t)c*HW + f*4);
        }
    }
    if (tid < 128){
        biasA[tid] = b_cl1[h*128 + tid];
        biasB[tid] = b_reg1[h*128 + tid];
        biasC[tid] = b_cl2[h*128 + tid];
        biasD[tid] = b_cl3[h*129 + tid];
        wsm[tid]   = w_cl3[(size_t)h*16512 + 128*128 + tid];
    }
    if (tid == 128) biasD[128] = b_cl3[h*129 + 128];
    // first run_stage prologue __syncthreads orders X/bias for all consumers

    ull acc[8][4];
    float mAcc[2] = {0.f, 0.f};

    // ---- Stage 1: reg1 (X -> xr global, [h][w][c]) ----
    ZERO_ACC();
    run_stage<false>(w_reg1 + (size_t)h*16384, X, WsB, acc, nullptr, mAcc);
    #pragma unroll
    for (int half = 0; half < 2; ++half){
        #pragma unroll
        for (int i = 0; i < 4; ++i){
            int w = wBase + t4 + i + half*64;
            float vv[8];
            #pragma unroll
            for (int o = 0; o < 8; ++o){
                float2 f2 = up2(acc[o][half*2 + (i>>1)]);
                vv[o] = lrelu(((i & 1) ? f2.y : f2.x) + biasB[o0 + o]);
            }
            float* dst = xr + (size_t)h*PHW + (size_t)w*128 + o0;
            *reinterpret_cast<float4*>(dst)     = make_float4(vv[0],vv[1],vv[2],vv[3]);
            *reinterpret_cast<float4*>(dst + 4) = make_float4(vv[4],vv[5],vv[6],vv[7]);
        }
    }

    // ---- Stage 2: cl1 (X -> X in place) ----
    ZERO_ACC();
    run_stage<false>(w_cl1 + (size_t)h*16384, X, WsB, acc, nullptr, mAcc);
    __syncthreads();                 // all reads of old X done before overwrite
    #pragma unroll
    for (int o = 0; o < 8; ++o){
        float bo = biasA[o0 + o];
        float2 a0 = up2(acc[o][0]), a1 = up2(acc[o][1]);
        float2 a2 = up2(acc[o][2]), a3 = up2(acc[o][3]);
        *reinterpret_cast<float4*>(&X[(o0+o)*128 + t4]) =
            make_float4(lrelu(a0.x+bo), lrelu(a0.y+bo), lrelu(a1.x+bo), lrelu(a1.y+bo));
        *reinterpret_cast<float4*>(&X[(o0+o)*128 + t4 + 64]) =
            make_float4(lrelu(a2.x+bo), lrelu(a2.y+bo), lrelu(a3.x+bo), lrelu(a3.y+bo));
    }
    // next run_stage's prologue sync orders these writes before its reads

    // ---- Stage 3: cl2 (X -> X in place) ----
    ZERO_ACC();
    run_stage<false>(w_cl2 + (size_t)h*16384, X, WsB, acc, nullptr, mAcc);
    __syncthreads();
    #pragma unroll
    for (int o = 0; o < 8; ++o){
        float bo = biasC[o0 + o];
        float2 a0 = up2(acc[o][0]), a1 = up2(acc[o][1]);
        float2 a2 = up2(acc[o][2]), a3 = up2(acc[o][3]);
        *reinterpret_cast<float4*>(&X[(o0+o)*128 + t4]) =
            make_float4(lrelu(a0.x+bo), lrelu(a0.y+bo), lrelu(a1.x+bo), lrelu(a1.y+bo));
        *reinterpret_cast<float4*>(&X[(o0+o)*128 + t4 + 64]) =
            make_float4(lrelu(a2.x+bo), lrelu(a2.y+bo), lrelu(a3.x+bo), lrelu(a3.y+bo));
    }

    // ---- Stage 4: cl3 + mask (X -> argmax) ----
    ZERO_ACC();
    run_stage<true>(w_cl3 + (size_t)h*16512, X, WsB, acc, wsm, mAcc);

    // per-thread argmax over its 8 classes for its 8 w (ascending class order,
    // strict > keeps first max like jnp.argmax)
    float bestv[8]; int besti[8];
    #pragma unroll
    for (int o = 0; o < 8; ++o){
        float bo = biasD[o0 + o];
        float2 p0 = up2(acc[o][0]), p1 = up2(acc[o][1]);
        float2 p2 = up2(acc[o][2]), p3 = up2(acc[o][3]);
        float vals[8] = {p0.x+bo, p0.y+bo, p1.x+bo, p1.y+bo,
                         p2.x+bo, p2.y+bo, p3.x+bo, p3.y+bo};
        #pragma unroll
        for (int j = 0; j < 8; ++j){
            if (o == 0){ bestv[j] = vals[j]; besti[j] = o0; }
            else if (vals[j] > bestv[j]){ bestv[j] = vals[j]; besti[j] = o0 + o; }
        }
    }
    __syncthreads();      // all FMA reads of WsB done; reuse it for reduction
    float* rv = WsB;                                  // [16 og][128 w]
    int*   ri = reinterpret_cast<int*>(WsB + 2048);   // [16 og][128 w]
    #pragma unroll
    for (int j = 0; j < 8; ++j){
        int w = (j < 4) ? (t4 + j) : (64 + t4 + j - 4);
        rv[og*128 + w] = bestv[j];
        ri[og*128 + w] = besti[j];
    }
    __syncthreads();
    if (tid < 128){
        float bv = rv[tid]; int bi = ri[tid];
        #pragma unroll
        for (int g = 1; g < 16; ++g){      // ascending class blocks: first max wins
            float v = rv[g*128 + tid];
            if (v > bv){ bv = v; bi = ri[g*128 + tid]; }
        }
        const int pg = h*WW + wBase + tid;
        inds[pg] = bi;
        outMask[pg] = lrelu(mAcc[0] + mAcc[1] + biasD[128]);
    }
}

// ---- final regressor: 8-lane sub-groups, 4 pixels per warp in flight ----
// lane = g*8+s; group g handles pixel p = base + it*4 + g; sublane s covers
// channels {s*4 + r*32}. 3 xor-shuffles reduce within the 8-lane group.
__global__ void __launch_bounds__(256)
k_final(const float* __restrict__ xrT, const int* __restrict__ inds,
        const float* __restrict__ w2, const float* __restrict__ b2,
        const float* __restrict__ w3, const float* __restrict__ b3,
        float* __restrict__ out)
{
    const int warp = (blockIdx.x * blockDim.x + threadIdx.x) >> 5;
    const int lane = threadIdx.x & 31;
    const int base = warp * 32;
    if (base >= HW) return;
    const int g = lane >> 3, s = lane & 7;

    #pragma unroll 1
    for (int it = 0; it < 8; ++it){
        const int p = base + it*4 + g;
        const int h = p >> 9, w = p & 511;
        const int n = w*HH + h;                       // reference's scrambled row id
        const int j = (n >> 9)*128 + __ldg(&inds[n]); // broadcast within group

        const float4* wp = reinterpret_cast<const float4*>(w2 + (size_t)j*512);
        const float*  xp = xrT + (size_t)h*PHW + (size_t)w*128;

        float4 a = make_float4(0.f, 0.f, 0.f, 0.f);
        #pragma unroll
        for (int r = 0; r < 4; ++r){
            int c = r*32 + s*4;                      // 4 consecutive channels
            float4 xv = *reinterpret_cast<const float4*>(xp + c);
            float4 w0 = __ldg(&wp[c]);
            float4 w1 = __ldg(&wp[c+1]);
            float4 w2v = __ldg(&wp[c+2]);
            float4 w3v = __ldg(&wp[c+3]);
            a.x = fmaf(xv.x, w0.x, a.x); a.y = fmaf(xv.x, w0.y, a.y);
            a.z = fmaf(xv.x, w0.z, a.z); a.w = fmaf(xv.x, w0.w, a.w);
            a.x = fmaf(xv.y, w1.x, a.x); a.y = fmaf(xv.y, w1.y, a.y);
            a.z = fmaf(xv.y, w1.z, a.z); a.w = fmaf(xv.y, w1.w, a.w);
            a.x = fmaf(xv.z, w2v.x, a.x); a.y = fmaf(xv.z, w2v.y, a.y);
            a.z = fmaf(xv.z, w2v.z, a.z); a.w = fmaf(xv.z, w2v.w, a.w);
            a.x = fmaf(xv.w, w3v.x, a.x); a.y = fmaf(xv.w, w3v.y, a.y);
            a.z = fmaf(xv.w, w3v.z, a.z); a.w = fmaf(xv.w, w3v.w, a.w);
        }
        #pragma unroll
        for (int d = 4; d > 0; d >>= 1){             // reduce within 8-lane group
            a.x += __shfl_xor_sync(0xffffffffu, a.x, d);
            a.y += __shfl_xor_sync(0xffffffffu, a.y, d);
            a.z += __shfl_xor_sync(0xffffffffu, a.z, d);
            a.w += __shfl_xor_sync(0xffffffffu, a.w, d);
        }
        if (s == 0){
            float4 bb  = *reinterpret_cast<const float4*>(b2 + 4*(size_t)j);
            float h0 = lrelu(a.x + bb.x), h1 = lrelu(a.y + bb.y);
            float h2 = lrelu(a.z + bb.z), h3 = lrelu(a.w + bb.w);
            float4 w3v = *reinterpret_cast<const float4*>(w3 + 4*(size_t)j);
            float r2 = b3[j];
            r2 = fmaf(h0, w3v.x, r2); r2 = fmaf(h1, w3v.y, r2);
            r2 = fmaf(h2, w3v.z, r2); r2 = fmaf(h3, w3v.w, r2);
            out[p] = ((float)__ldg(&inds[p]) + r2) * (1.0f/128.0f);
        }
    }
}

extern "C" void kernel_launch(void* const* d_in, const int* in_sizes, int n_in,
                              void* d_out, int out_size)
{
    (void)in_sizes; (void)n_in; (void)out_size;
    const float* x_in  = (const float*)d_in[0];
    const float* w_cl1 = (const float*)d_in[1];
    const float* b_cl1 = (const float*)d_in[2];
    const float* w_cl2 = (const float*)d_in[3];
    const float* b_cl2 = (const float*)d_in[4];
    const float* w_cl3 = (const float*)d_in[5];
    const float* b_cl3 = (const float*)d_in[6];
    const float* w_reg1= (const float*)d_in[7];
    const float* b_reg1= (const float*)d_in[8];
    const float* w2    = (const float*)d_in[9];
    const float* b2    = (const float*)d_in[10];
    const float* w3    = (const float*)d_in[11];
    const float* b3    = (const float*)d_in[12];
    float* out = (float*)d_out;

    float* xr; int* inds;
    cudaGetSymbolAddress((void**)&xr, g_xr);
    cudaGetSymbolAddress((void**)&inds, g_inds);

    const int smemB = SM_FLOATS * 4;   // ~82.5KB -> 2 CTAs/SM
    cudaFuncSetAttribute(k_fused, cudaFuncAttributeMaxDynamicSharedMemorySize, smemB);

    k_fused<<<dim3(4, HH), 256, smemB>>>(x_in,
                                         w_cl1, b_cl1, w_reg1, b_reg1,
                                         w_cl2, b_cl2, w_cl3, b_cl3,
                                         xr, inds, out + HW);
    k_final<<<HW/32/8, 256>>>(xr, inds, w2, b2, w3, b3, out);
}

// round 11
// speedup vs baseline: 1.5987x; 1.5987x over previous
#include <cuda_runtime.h>
#include <cstdint>

#define HH 448
#define WW 512
#define HW (HH*WW)        // 229376
#define CHW 65536         // per-h activation plane: 128*512 (or [w][c] = 512*128)

typedef unsigned long long ull;

// scratch (allocation-free rule)
__device__ float g_t1[(size_t)HH*CHW];      // [h][c][w]
__device__ float g_t2[(size_t)HH*CHW];      // [h][c][w]
__device__ float g_xr[(size_t)HH*CHW];      // TRANSPOSED: [h][w][c]
__device__ int   g_inds[HW];

__device__ __forceinline__ ull pk2(float v){
    ull r; unsigned u = __float_as_uint(v);
    asm("mov.b64 %0, {%1, %1};" : "=l"(r) : "r"(u));
    return r;
}
__device__ __forceinline__ void fma2(ull& d, ull a, ull b){
    asm("fma.rn.f32x2 %0, %1, %2, %0;" : "+l"(d) : "l"(a), "l"(b));
}
__device__ __forceinline__ float2 up2(ull v){
    unsigned lo, hi;
    asm("mov.b64 {%0, %1}, %2;" : "=r"(lo), "=r"(hi) : "l"(v));
    return make_float2(__uint_as_float(lo), __uint_as_float(hi));
}
__device__ __forceinline__ float lrelu(float v){ return v >= 0.f ? v : 0.01f*v; }

// Core: one CTA computes a 128(O) x 128(W) tile for row h, K=128.
// Both X and W streamed from global in 8 chunks of 16 k, double-buffered.
// acc[8][4]: thread covers o0..o0+7 and w-cols {t4..t4+3, t4+64..t4+67}.
// If MASK: threads tid<128 also accumulate the 129th classifier row
// (mAcc partials, col = tid) from the resident X chunk.
template<bool MASK>
__device__ __forceinline__ void gemm_core(
    const float* __restrict__ Xh, size_t xRS,
    const float* __restrict__ Wh,
    float (&Ws)[2][16][128], float (&Xs)[2][16][128],
    ull (&acc)[8][4],
    const float* __restrict__ wsm, float* __restrict__ mAcc)
{
    const int tid = threadIdx.x;
    const int og = tid >> 4, wg = tid & 15;
    const int o0 = og << 3, t4 = wg << 2;
    const int xk = tid >> 4;            // Xs load: row within chunk (16 rows)
    const int xc = (tid & 15) << 2;     // Xs load: col base (2 float4 / thread)
    const int wq = tid & 3;             // Ws load: k-quad
    const int wo = tid >> 2;            // Ws load: o (0..63, +64)

    float4 xst0, xst1, wst0, wst1;

    // prologue: chunk 0
    xst0 = *reinterpret_cast<const float4*>(Xh + (size_t)xk * xRS + xc);
    xst1 = *reinterpret_cast<const float4*>(Xh + (size_t)xk * xRS + xc + 64);
    wst0 = *reinterpret_cast<const float4*>(Wh + wo*128 + wq*4);
    wst1 = *reinterpret_cast<const float4*>(Wh + (wo+64)*128 + wq*4);
    *reinterpret_cast<float4*>(&Xs[0][xk][xc])      = xst0;
    *reinterpret_cast<float4*>(&Xs[0][xk][xc + 64]) = xst1;
    {
        const float* s0 = &wst0.x; const float* s1 = &wst1.x;
        #pragma unroll
        for (int i = 0; i < 4; ++i){
            int k = wq*4 + i;
            Ws[0][k][wo ^ (wq<<3)] = s0[i];          // XOR swizzle: conflict-free
            Ws[0][k][(wo+64) ^ (wq<<3)] = s1[i];
        }
    }
    __syncthreads();

    int buf = 0;
    #pragma unroll 1
    for (int ch = 0; ch < 8; ++ch){
        if (ch < 7){
            int k0 = (ch+1)*16;
            xst0 = *reinterpret_cast<const float4*>(Xh + (size_t)(k0 + xk) * xRS + xc);
            xst1 = *reinterpret_cast<const float4*>(Xh + (size_t)(k0 + xk) * xRS + xc + 64);
            wst0 = *reinterpret_cast<const float4*>(Wh + wo*128 + k0 + wq*4);
            wst1 = *reinterpret_cast<const float4*>(Wh + (wo+64)*128 + k0 + wq*4);
        }
        #pragma unroll
        for (int k = 0; k < 16; ++k){
            int wOff = ((k >> 2) & 3) << 3;
            const float4* wr = reinterpret_cast<const float4*>(&Ws[buf][k][o0 ^ wOff]);
            float4 wa = wr[0], wb2 = wr[1];
            float wv[8] = {wa.x,wa.y,wa.z,wa.w,wb2.x,wb2.y,wb2.z,wb2.w};
            ulonglong2 v0 = *reinterpret_cast<const ulonglong2*>(&Xs[buf][k][t4]);
            ulonglong2 v1 = *reinterpret_cast<const ulonglong2*>(&Xs[buf][k][t4 + 64]);
            #pragma unroll
            for (int o = 0; o < 8; ++o){
                ull wp = pk2(wv[o]);
                fma2(acc[o][0], v0.x, wp);
                fma2(acc[o][1], v0.y, wp);
                fma2(acc[o][2], v1.x, wp);
                fma2(acc[o][3], v1.y, wp);
            }
        }
        if (MASK && tid < 128){
            #pragma unroll
            for (int k = 0; k < 16; k += 2){
                mAcc[0] = fmaf(Xs[buf][k][tid],   wsm[ch*16 + k],     mAcc[0]);
                mAcc[1] = fmaf(Xs[buf][k+1][tid], wsm[ch*16 + k + 1], mAcc[1]);
            }
        }
        if (ch < 7){
            int nb = buf ^ 1;
            *reinterpret_cast<float4*>(&Xs[nb][xk][xc])      = xst0;
            *reinterpret_cast<float4*>(&Xs[nb][xk][xc + 64]) = xst1;
            const float* s0 = &wst0.x; const float* s1 = &wst1.x;
            #pragma unroll
            for (int i = 0; i < 4; ++i){
                int k = wq*4 + i;
                Ws[nb][k][wo ^ (wq<<3)] = s0[i];
                Ws[nb][k][(wo+64) ^ (wq<<3)] = s1[i];
            }
            __syncthreads();
            buf = nb;
        }
    }
}

#define ZERO_ACC(acc) do { _Pragma("unroll") for(int o=0;o<8;o++){ _Pragma("unroll") for(int q=0;q<4;q++) (acc)[o][q]=0ull; } } while(0)

// GEMM + bias + leaky-relu. dual: blockIdx.x&1 selects weight set A/B
// (interleaved so both read the same X tile back-to-back -> L2 reuse).
// sel==1 with transB stores output TRANSPOSED as [h][w][o] (for k_final).
__global__ void __launch_bounds__(256, 2)
k_gemm_lrelu(const float* __restrict__ X, size_t xHS, size_t xRS,
             const float* __restrict__ WtA, const float* __restrict__ BtA, float* __restrict__ YA,
             const float* __restrict__ WtB, const float* __restrict__ BtB, float* __restrict__ YB,
             int dual, int transB)
{
    __shared__ __align__(16) float Ws[2][16][128];
    __shared__ __align__(16) float Xs[2][16][128];
    int bx = blockIdx.x;
    int sel = 0, wTile;
    if (dual){ sel = bx & 1; wTile = bx >> 1; } else wTile = bx;
    const int h = blockIdx.y;
    const int wBase = wTile * 128;
    const float* Wt = sel ? WtB : WtA;
    const float* Bt = sel ? BtB : BtA;
    float* Y = sel ? YB : YA;

    ull acc[8][4];
    ZERO_ACC(acc);

    const float* Xh = X + (size_t)h*xHS + wBase;
    const float* Wh = Wt + (size_t)h*16384;
    float mDummy[2];
    gemm_core<false>(Xh, xRS, Wh, Ws, Xs, acc, nullptr, mDummy);

    const int tid = threadIdx.x;
    const int og = tid>>4, wg = tid&15;
    const int o0 = og<<3, t4 = wg<<2;

    if (sel == 1 && transB){
        // transposed store: (o, w) -> Y[h*CHW + w*128 + o]
        #pragma unroll
        for (int half = 0; half < 2; ++half){
            #pragma unroll
            for (int i = 0; i < 4; ++i){
                int w = wBase + t4 + i + half*64;
                float vv[8];
                #pragma unroll
                for (int o = 0; o < 8; ++o){
                    float2 f2 = up2(acc[o][half*2 + (i>>1)]);
                    vv[o] = lrelu(((i & 1) ? f2.y : f2.x) + Bt[h*128 + o0 + o]);
                }
                float* dst = Y + (size_t)h*CHW + (size_t)w*128 + o0;
                *reinterpret_cast<float4*>(dst)     = make_float4(vv[0],vv[1],vv[2],vv[3]);
                *reinterpret_cast<float4*>(dst + 4) = make_float4(vv[4],vv[5],vv[6],vv[7]);
            }
        }
    } else {
        #pragma unroll
        for (int o = 0; o < 8; ++o){
            float bo = Bt[h*128 + o0 + o];
            float* yo = Y + (size_t)h*CHW + (size_t)(o0+o)*WW + wBase;
            float2 a0 = up2(acc[o][0]), a1 = up2(acc[o][1]);
            float2 a2 = up2(acc[o][2]), a3 = up2(acc[o][3]);
            *reinterpret_cast<float4*>(yo + t4) =
                make_float4(lrelu(a0.x+bo), lrelu(a0.y+bo), lrelu(a1.x+bo), lrelu(a1.y+bo));
            *reinterpret_cast<float4*>(yo + t4 + 64) =
                make_float4(lrelu(a2.x+bo), lrelu(a2.y+bo), lrelu(a3.x+bo), lrelu(a3.y+bo));
        }
    }
}

// Classifier GEMM (129-row weights) + fused mask row + fused in-CTA argmax.
// Tile covers all 128 classes x 128 cols -> logits never leave the CTA.
__global__ void __launch_bounds__(256, 2)
k_gemm_argmax(const float* __restrict__ X, const float* __restrict__ Wt,
              const float* __restrict__ Bt, int* __restrict__ inds,
              float* __restrict__ outMask)
{
    __shared__ __align__(16) float Ws[2][16][128];
    __shared__ __align__(16) float Xs[2][16][128];
    __shared__ float wsm[128];
    __shared__ float biasD[129];
    const int wTile = blockIdx.x, h = blockIdx.y;
    const int wBase = wTile * 128;
    const int tid = threadIdx.x;

    if (tid < 128){
        wsm[tid] = Wt[(size_t)h*16512 + 128*128 + tid];
        biasD[tid] = Bt[h*129 + tid];
    }
    if (tid == 128) biasD[128] = Bt[h*129 + 128];
    // ordered by gemm_core's prologue __syncthreads

    ull acc[8][4];
    ZERO_ACC(acc);
    float mAcc[2] = {0.f, 0.f};

    const float* Xh = X + (size_t)h*CHW + wBase;
    const float* Wh = Wt + (size_t)h*16512;
    gemm_core<true>(Xh, (size_t)WW, Wh, Ws, Xs, acc, wsm, mAcc);

    const int og = tid>>4, wg = tid&15;
    const int o0 = og<<3, t4 = wg<<2;

    // per-thread argmax over its 8 classes for its 8 w (ascending class order,
    // strict > keeps the first max like jnp.argmax)
    float bestv[8]; int besti[8];
    #pragma unroll
    for (int o = 0; o < 8; ++o){
        float bo = biasD[o0 + o];
        float2 p0 = up2(acc[o][0]), p1 = up2(acc[o][1]);
        float2 p2 = up2(acc[o][2]), p3 = up2(acc[o][3]);
        float vals[8] = {p0.x+bo, p0.y+bo, p1.x+bo, p1.y+bo,
                         p2.x+bo, p2.y+bo, p3.x+bo, p3.y+bo};
        #pragma unroll
        for (int j = 0; j < 8; ++j){
            if (o == 0){ bestv[j] = vals[j]; besti[j] = o0; }
            else if (vals[j] > bestv[j]){ bestv[j] = vals[j]; besti[j] = o0 + o; }
        }
    }
    __syncthreads();    // all FMA reads of Ws done; reuse it for the reduction
    float* rv = &Ws[0][0][0];                         // [16 og][128 w]
    int*   ri = reinterpret_cast<int*>(&Ws[1][0][0]); // [16 og][128 w]
    #pragma unroll
    for (int j = 0; j < 8; ++j){
        int w = (j < 4) ? (t4 + j) : (64 + t4 + j - 4);
        rv[og*128 + w] = bestv[j];
        ri[og*128 + w] = besti[j];
    }
    __syncthreads();
    if (tid < 128){
        float bv = rv[tid]; int bi = ri[tid];
        #pragma unroll
        for (int g = 1; g < 16; ++g){     // ascending class blocks: first max wins
            float v = rv[g*128 + tid];
            if (v > bv){ bv = v; bi = ri[g*128 + tid]; }
        }
        const int pg = h*WW + wBase + tid;
        inds[pg] = bi;
        outMask[pg] = lrelu(mAcc[0] + mAcc[1] + biasD[128]);
    }
}

// Final: gathered per-pixel 128->4->1 regressor, warp-cooperative (proven R4).
// One warp = 32 consecutive pixels; per pixel the 32 lanes split the 128
// channels (coalesced xr + w2 reads), butterfly-shuffle reduce.
// Reproduces the reference's index scramble: rows use n = w*448 + h, while
// inds_r interprets the same flat n as (h2, w2i) on a (448,512) grid.
__global__ void __launch_bounds__(256)
k_final(const float* __restrict__ xrT, const int* __restrict__ inds,
        const float* __restrict__ w2, const float* __restrict__ b2,
        const float* __restrict__ w3, const float* __restrict__ b3,
        float* __restrict__ out)
{
    const int warp = (blockIdx.x * blockDim.x + threadIdx.x) >> 5;
    const int lane = threadIdx.x & 31;
    const int base = warp * 32;
    if (base >= HW) return;

    float res = 0.f;
    #pragma unroll 1
    for (int i = 0; i < 32; ++i){
        const int p = base + i;
        const int h = p >> 9, w = p & 511;
        const int n = w*HH + h;
        const int j = (n >> 9)*128 + __ldg(&inds[n]);   // broadcast load

        const float4* wp = reinterpret_cast<const float4*>(w2 + (size_t)j*512);
        const float*  xp = xrT + (size_t)h*CHW + (size_t)w*128;

        float4 a = make_float4(0.f, 0.f, 0.f, 0.f);
        #pragma unroll
        for (int r = 0; r < 4; ++r){
            int c = r*32 + lane;
            float  xv = __ldg(&xp[c]);      // coalesced 128B per round
            float4 wv = __ldg(&wp[c]);      // coalesced 512B per round
            a.x = fmaf(xv, wv.x, a.x);
            a.y = fmaf(xv, wv.y, a.y);
            a.z = fmaf(xv, wv.z, a.z);
            a.w = fmaf(xv, wv.w, a.w);
        }
        #pragma unroll
        for (int s = 16; s > 0; s >>= 1){
            a.x += __shfl_xor_sync(0xffffffffu, a.x, s);
            a.y += __shfl_xor_sync(0xffffffffu, a.y, s);
            a.z += __shfl_xor_sync(0xffffffffu, a.z, s);
            a.w += __shfl_xor_sync(0xffffffffu, a.w, s);
        }
        if (lane == i){
            float4 bb  = *reinterpret_cast<const float4*>(b2 + 4*(size_t)j);
            float h0 = lrelu(a.x + bb.x), h1 = lrelu(a.y + bb.y);
            float h2 = lrelu(a.z + bb.z), h3 = lrelu(a.w + bb.w);
            float4 w3v = *reinterpret_cast<const float4*>(w3 + 4*(size_t)j);
            float r2 = b3[j];
            r2 = fmaf(h0, w3v.x, r2); r2 = fmaf(h1, w3v.y, r2);
            r2 = fmaf(h2, w3v.z, r2); r2 = fmaf(h3, w3v.w, r2);
            res = ((float)inds[p] + r2) * (1.0f/128.0f);
        }
    }
    out[base + lane] = res;   // coalesced store of the warp's 32 results
}

extern "C" void kernel_launch(void* const* d_in, const int* in_sizes, int n_in,
                              void* d_out, int out_size)
{
    (void)in_sizes; (void)n_in; (void)out_size;
    const float* x_in  = (const float*)d_in[0];
    const float* w_cl1 = (const float*)d_in[1];
    const float* b_cl1 = (const float*)d_in[2];
    const float* w_cl2 = (const float*)d_in[3];
    const float* b_cl2 = (const float*)d_in[4];
    const float* w_cl3 = (const float*)d_in[5];
    const float* b_cl3 = (const float*)d_in[6];
    const float* w_reg1= (const float*)d_in[7];
    const float* b_reg1= (const float*)d_in[8];
    const float* w2    = (const float*)d_in[9];
    const float* b2    = (const float*)d_in[10];
    const float* w3    = (const float*)d_in[11];
    const float* b3    = (const float*)d_in[12];
    float* out = (float*)d_out;

    float *t1, *t2, *xr; int* inds;
    cudaGetSymbolAddress((void**)&t1, g_t1);
    cudaGetSymbolAddress((void**)&t2, g_t2);
    cudaGetSymbolAddress((void**)&xr, g_xr);
    cudaGetSymbolAddress((void**)&inds, g_inds);

    // x_in[c][h][w]: per-h base stride 512, channel stride H*W
    // L1 dual: cl1 -> t1 [h][c][w]; reg1 -> xr TRANSPOSED [h][w][c]
    k_gemm_lrelu<<<dim3(8, HH), 256>>>(x_in, (size_t)WW, (size_t)HW,
                                       w_cl1, b_cl1, t1,
                                       w_reg1, b_reg1, xr, 1, 1);
    // L2: t1 -> t2
    k_gemm_lrelu<<<dim3(4, HH), 256>>>(t1, (size_t)CHW, (size_t)WW,
                                       w_cl2, b_cl2, t2,
                                       nullptr, nullptr, nullptr, 0, 0);
    // L3: t2 -> inds + mask (logits stay on-chip)
    k_gemm_argmax<<<dim3(4, HH), 256>>>(t2, w_cl3, b_cl3, inds, out + HW);
    // regressor -> out[0:HW)
    k_final<<<HW/32/8, 256>>>(xr, inds, w2, b2, w3, b3, out);
}